// round 16
// baseline (speedup 1.0000x reference)
#include <cuda_runtime.h>
#include <math_constants.h>

#define BB 32
#define CC 64
#define NN 8192
#define SS 64

typedef unsigned long long ull;

// ---------------- device scratch ----------------
__device__ float g_yT[(size_t)BB*NN*CC];    // conv output transposed: [b][n][c]
__device__ float g_proj[(size_t)BB*3*NN];   // W_off @ fea: [b][3][n]
__device__ float g_nodeloc[BB*SS*3];
__device__ int   g_fidx[BB*SS];
__device__ float g_sum[CC];
__device__ float g_sq[CC];

__device__ __forceinline__ void cp_async16(void* smem_dst, const void* gmem_src) {
    unsigned sa = (unsigned)__cvta_generic_to_shared(smem_dst);
    asm volatile("cp.async.ca.shared.global [%0], [%1], 16;" :: "r"(sa), "l"(gmem_src));
}
__device__ __forceinline__ void cp_commit() { asm volatile("cp.async.commit_group;"); }
__device__ __forceinline__ void cp_wait0()  { asm volatile("cp.async.wait_group 0;"); }

// ---- f32x2 helpers (lanewise FFMA pair; bit-identical to 2x scalar fmaf) --
__device__ __forceinline__ ull bcast2(float f) {
    ull r; asm("mov.b64 %0,{%1,%1};" : "=l"(r) : "f"(f)); return r;
}
__device__ __forceinline__ void fma2(ull &acc, ull a, ull b) {
    asm("fma.rn.f32x2 %0,%1,%2,%0;" : "+l"(acc) : "l"(a), "l"(b));
}
__device__ __forceinline__ void unpack2(ull v, float &lo, float &hi) {
    asm("mov.b64 {%0,%1},%2;" : "=f"(lo), "=f"(hi) : "l"(v));
}

// ---------------- K0: zero BN accumulators ----------------
__global__ void k_zero() {
    int i = threadIdx.x;
    if (i < CC) { g_sum[i] = 0.f; g_sq[i] = 0.f; }
}

// ---------------- K1: farthest point sampling (loc staged in smem) --------
__device__ __forceinline__ void amax2(float &v, int &i, float v2, int i2) {
    if (v2 > v || (v2 == v && i2 < i)) { v = v2; i = i2; }
}

__global__ void k_fps(const float* __restrict__ loc) {
    extern __shared__ float sloc[];         // [3*NN] = 96KB
    int b = blockIdx.x;
    int t = threadIdx.x;
    const float* L = loc + (size_t)b*3*NN;
    for (int i = t; i < 3*NN; i += 1024) sloc[i] = L[i];
    __shared__ float swv[32];
    __shared__ int   swi[32];
    __shared__ int   s_far;
    if (t == 0) s_far = 0;
    __syncthreads();
    float px[8], py[8], pz[8], pd[8];
#pragma unroll
    for (int j = 0; j < 8; ++j) {
        int n = j*1024 + t;
        px[j] = sloc[n]; py[j] = sloc[NN+n]; pz[j] = sloc[2*NN+n];
        pd[j] = 1e10f;
    }
    int lane = t & 31, wid = t >> 5;
    for (int it = 0; it < SS; ++it) {
        int far = s_far;
        if (t == 0) g_fidx[b*SS + it] = far;
        float cx = sloc[far], cy = sloc[NN+far], cz = sloc[2*NN+far];
        float bv = -1.f; int bi = 0;
#pragma unroll
        for (int j = 0; j < 8; ++j) {
            float dx = px[j] - cx;
            float dy = py[j] - cy;
            float dz = pz[j] - cz;
            float d  = __fmaf_rn(dz, dz, __fmaf_rn(dy, dy, __fmul_rn(dx, dx)));
            float nd = fminf(pd[j], d);
            pd[j] = nd;
            if (nd > bv) { bv = nd; bi = j*1024 + t; }
        }
#pragma unroll
        for (int off = 16; off; off >>= 1) {
            float v2 = __shfl_down_sync(0xffffffffu, bv, off);
            int   i2 = __shfl_down_sync(0xffffffffu, bi, off);
            amax2(bv, bi, v2, i2);
        }
        if (lane == 0) { swv[wid] = bv; swi[wid] = bi; }
        __syncthreads();
        if (wid == 0) {
            bv = swv[lane]; bi = swi[lane];
#pragma unroll
            for (int off = 16; off; off >>= 1) {
                float v2 = __shfl_down_sync(0xffffffffu, bv, off);
                int   i2 = __shfl_down_sync(0xffffffffu, bi, off);
                amax2(bv, bi, v2, i2);
            }
            if (lane == 0) s_far = bi;
        }
        __syncthreads();
    }
}

// ---------------- K2: fused GEMM + proj + copy-out + BN stats -------------
__global__ void __launch_bounds__(256, 3) k_gemm(const float* __restrict__ fea,
                                                 const float* __restrict__ Wres,
                                                 const float* __restrict__ bres,
                                                 const float* __restrict__ Woff,
                                                 float* __restrict__ out) {
    __shared__ float sWt[CC*CC];        // transposed: [c][o], 16KB
    __shared__ float sWo[3*CC];
    __shared__ float sF[2][8*128];
    __shared__ float sstat[2*CC];
    int b = blockIdx.y, base = blockIdx.x * 128, tid = threadIdx.x;
    for (int i = tid; i < CC*CC; i += 256) { int o = i >> 6, c = i & 63; sWt[c*CC + o] = Wres[i]; }
    for (int i = tid; i < 3*CC; i += 256) sWo[i] = Woff[i];
    if (tid < 2*CC) sstat[tid] = 0.f;
    int ogrp = tid >> 6, nl = tid & 63, o0 = ogrp * 16;
    int lane = tid & 31;
    const float* F = fea + (size_t)b*CC*NN + base;
    float* O0 = out + (size_t)b*2*CC*NN + base;
    int lc = tid >> 5;
    int lcol = (tid & 31) * 4;
    ull acc0[8], acc1[8];
#pragma unroll
    for (int q = 0; q < 8; ++q) { acc0[q] = 0ull; acc1[q] = 0ull; }
    float pj[3][2] = {{0.f,0.f},{0.f,0.f},{0.f,0.f}};
    cp_async16(&sF[0][lc*128 + lcol], &F[(size_t)lc*NN + lcol]);
    cp_commit();
    for (int ch = 0; ch < 8; ++ch) {
        int buf = ch & 1;
        cp_wait0();
        __syncthreads();
        if (ch < 7) {
            cp_async16(&sF[buf^1][lc*128 + lcol], &F[(size_t)((ch+1)*8 + lc)*NN + lcol]);
            cp_commit();
        }
        *(float4*)&O0[(size_t)(ch*8 + lc)*NN + lcol] = *(float4*)&sF[buf][lc*128 + lcol];
#pragma unroll
        for (int cc = 0; cc < 8; ++cc) {
            int c = ch*8 + cc;
            float f0 = sF[buf][cc*128 + nl];
            float f1 = sF[buf][cc*128 + 64 + nl];
            const longlong2* W2 = (const longlong2*)&sWt[c*CC + o0];  // 16 floats = 8 ull
            longlong2 wa = W2[0], wb = W2[1], wc = W2[2], wd = W2[3];
            ull ff0 = bcast2(f0), ff1 = bcast2(f1);
            fma2(acc0[0], (ull)wa.x, ff0);  fma2(acc1[0], (ull)wa.x, ff1);
            fma2(acc0[1], (ull)wa.y, ff0);  fma2(acc1[1], (ull)wa.y, ff1);
            fma2(acc0[2], (ull)wb.x, ff0);  fma2(acc1[2], (ull)wb.x, ff1);
            fma2(acc0[3], (ull)wb.y, ff0);  fma2(acc1[3], (ull)wb.y, ff1);
            fma2(acc0[4], (ull)wc.x, ff0);  fma2(acc1[4], (ull)wc.x, ff1);
            fma2(acc0[5], (ull)wc.y, ff0);  fma2(acc1[5], (ull)wc.y, ff1);
            fma2(acc0[6], (ull)wd.x, ff0);  fma2(acc1[6], (ull)wd.x, ff1);
            fma2(acc0[7], (ull)wd.y, ff0);  fma2(acc1[7], (ull)wd.y, ff1);
            if (ogrp == 1) {
                float v0 = sWo[c], v1 = sWo[64+c], v2 = sWo[128+c];
                pj[0][0] = fmaf(v0, f0, pj[0][0]); pj[0][1] = fmaf(v0, f1, pj[0][1]);
                pj[1][0] = fmaf(v1, f0, pj[1][0]); pj[1][1] = fmaf(v1, f1, pj[1][1]);
                pj[2][0] = fmaf(v2, f0, pj[2][0]); pj[2][1] = fmaf(v2, f1, pj[2][1]);
            }
        }
    }
    if (ogrp == 1) {
        float* P = g_proj + (size_t)b*3*NN + base + nl;
        P[0]        = pj[0][0];  P[64]        = pj[0][1];
        P[NN]       = pj[1][0];  P[NN+64]     = pj[1][1];
        P[2*NN]     = pj[2][0];  P[2*NN+64]   = pj[2][1];
    }
    float bb[16];
#pragma unroll
    for (int q = 0; q < 16; ++q) bb[q] = bres[o0+q];
    float s1v[16], s2v[16];
#pragma unroll
    for (int q = 0; q < 16; ++q) { s1v[q] = 0.f; s2v[q] = 0.f; }
    float* YT = g_yT + (size_t)b*NN*CC;
#pragma unroll
    for (int j = 0; j < 2; ++j) {
        float v[16];
#pragma unroll
        for (int q = 0; q < 8; ++q) {
            ull a = j ? acc1[q] : acc0[q];
            unpack2(a, v[2*q], v[2*q+1]);       // lo = channel o0+2q
        }
#pragma unroll
        for (int q = 0; q < 16; ++q) {
            v[q] = v[q] + bb[q];
            s1v[q] += v[q];
            s2v[q] = fmaf(v[q], v[q], s2v[q]);
        }
        float4* dst = (float4*)(YT + (size_t)(base + j*64 + nl)*CC + o0);
        dst[0] = make_float4(v[0],v[1],v[2],v[3]);
        dst[1] = make_float4(v[4],v[5],v[6],v[7]);
        dst[2] = make_float4(v[8],v[9],v[10],v[11]);
        dst[3] = make_float4(v[12],v[13],v[14],v[15]);
    }
#pragma unroll
    for (int off = 16; off; off >>= 1)
#pragma unroll
        for (int q = 0; q < 16; ++q) {
            s1v[q] += __shfl_xor_sync(0xffffffffu, s1v[q], off);
            s2v[q] += __shfl_xor_sync(0xffffffffu, s2v[q], off);
        }
    if (lane == 0) {
#pragma unroll
        for (int q = 0; q < 16; ++q) {
            atomicAdd(&sstat[o0+q], s1v[q]);
            atomicAdd(&sstat[64+o0+q], s2v[q]);
        }
    }
    __syncthreads();
    if (tid < 64)       atomicAdd(&g_sum[tid], sstat[tid]);
    else if (tid < 128) atomicAdd(&g_sq[tid-64], sstat[tid]);
}

// ---------------- bin picker: block-wide k-th bin over nbpt*256 bins ------
__device__ __forceinline__ void pick_bins(const int* h, int nbpt, int kwant,
                                          int tid, int lane, int wid,
                                          int* s_w8, unsigned* sbin, int* skk) {
    int base = tid * nbpt;
    int ssum = 0;
    for (int i = 0; i < nbpt; ++i) ssum += h[base+i];
    int inc = ssum;
#pragma unroll
    for (int off = 1; off < 32; off <<= 1) {
        int v = __shfl_up_sync(0xffffffffu, inc, off);
        if (lane >= off) inc += v;
    }
    if (lane == 31) s_w8[wid] = inc;
    __syncthreads();
    if (wid == 0 && lane < 8) {
        int y = s_w8[lane];
#pragma unroll
        for (int off = 1; off < 8; off <<= 1) {
            int v = __shfl_up_sync(0x000000ffu, y, off);
            if (lane >= off) y += v;
        }
        s_w8[lane] = y;
    }
    __syncthreads();
    int pre = inc - ssum + (wid ? s_w8[wid-1] : 0);
    if (pre < kwant && pre + ssum >= kwant) {
        int cum = pre;
        for (int i = 0; i < nbpt; ++i) {
            int hv = h[base+i];
            if (cum + hv >= kwant) { *sbin = (unsigned)(base+i); *skk = kwant - cum; break; }
            cum += hv;
        }
    }
    __syncthreads();
}

// order-preserving key from xyz; single definition -> bit-identical everywhere
__device__ __forceinline__ unsigned key_xyz(float x, float y, float z,
                                            float nx, float ny, float nz, float ns2) {
    float dot = __fmaf_rn(nz, z, __fmaf_rn(ny, y, __fmul_rn(nx, x)));
    float ps2 = __fmaf_rn(z, z, __fmaf_rn(y, y, __fmul_rn(x, x)));
    float d   = __fadd_rn(__fadd_rn(__fmul_rn(-2.f, dot), ns2), ps2);
    unsigned u = __float_as_uint(d);
    return (u & 0x80000000u) ? ~u : (u | 0x80000000u);
}
__device__ __forceinline__ unsigned dist_key(const float* __restrict__ L, int n,
                                             float nx, float ny, float nz, float ns2) {
    return key_xyz(L[n], L[NN+n], L[2*NN+n], nx, ny, nz, ns2);
}

// ------ K3: fused ball-query offset + 64-NN select + node_fea -------------
__global__ void __launch_bounds__(256) k_select(const float* __restrict__ loc,
                                                const float* __restrict__ gamma,
                                                const float* __restrict__ beta,
                                                float* __restrict__ out_nf,
                                                float* __restrict__ out_off) {
    __shared__ int hist[4096];             // 16KB (reused at 1024/256 granularity)
    __shared__ int cand[1024];
    __shared__ unsigned candk[1024];
    __shared__ int sel[64];
    __shared__ int eq[128];
    __shared__ int bsel[64];
    __shared__ float snode[4];
    __shared__ int s_w8[8];
    __shared__ unsigned sbin;
    __shared__ int skk;
    __shared__ int scnt, ccnt, eqcnt;
    __shared__ float smx[256], smn[256];
    int id = blockIdx.x;
    int b = id >> 6, s = id & 63;
    int tid = threadIdx.x;
    int lane = tid & 31, wid = tid >> 5;
    unsigned lml = (1u << lane) - 1u;
    const float* L = loc + (size_t)b*3*NN;

    // warps 1..7 zero hist + counters while warp 0 does ball query + offset
    if (wid > 0) {
        for (int i = tid - 32; i < 4096; i += 224) hist[i] = 0;
        if (tid == 32) { scnt = 0; ccnt = 0; eqcnt = 0; }
    } else {
        const float* P = g_proj + (size_t)b*3*NN;
        int nidx = g_fidx[id];
        float fx = L[nidx], fy = L[NN+nidx], fz = L[2*NN+nidx];
        float fs2 = __fmaf_rn(fz, fz, __fmaf_rn(fy, fy, __fmul_rn(fx, fx)));
        const float r2 = (float)(0.3*0.3);
        int cnt = 0;
        for (int basei = 0; basei < NN && cnt < 64; basei += 32) {
            int n = basei + lane;
            float x = L[n], y = L[NN+n], z = L[2*NN+n];
            float dot = __fmaf_rn(fz, z, __fmaf_rn(fy, y, __fmul_rn(fx, x)));
            float ps2 = __fmaf_rn(z, z, __fmaf_rn(y, y, __fmul_rn(x, x)));
            float d   = __fadd_rn(__fadd_rn(__fmul_rn(-2.f, dot), fs2), ps2);
            bool ok = !(d > r2);
            unsigned m = __ballot_sync(0xffffffffu, ok);
            int pos = cnt + __popc(m & lml);
            if (ok && pos < 64) bsel[pos] = n;
            cnt += __popc(m);
        }
        if (cnt > 64) cnt = 64;
        __syncwarp();
        for (int k = cnt + lane; k < 64; k += 32) bsel[k] = bsel[0];
        __syncwarp();
        float p0n = P[nidx], p1n = P[NN+nidx], p2n = P[2*NN+nidx];
        float a0 = 0.f, a1 = 0.f, a2 = 0.f;
#pragma unroll
        for (int k = lane; k < 64; k += 32) {
            int idx = bsel[k];
            float t0 = tanhf(P[idx]      - p0n);
            float t1 = tanhf(P[NN+idx]   - p1n);
            float t2 = tanhf(P[2*NN+idx] - p2n);
            a0 = fmaf(t0, L[idx] - fx, a0);
            a1 = fmaf(t1, L[NN+idx] - fy, a1);
            a2 = fmaf(t2, L[2*NN+idx] - fz, a2);
        }
#pragma unroll
        for (int off = 16; off; off >>= 1) {
            a0 += __shfl_xor_sync(0xffffffffu, a0, off);
            a1 += __shfl_xor_sync(0xffffffffu, a1, off);
            a2 += __shfl_xor_sync(0xffffffffu, a2, off);
        }
        if (lane == 0) {
            float o0 = a0 * (1.f/64.f), o1 = a1 * (1.f/64.f), o2 = a2 * (1.f/64.f);
            out_off[b*3*SS + 0*SS + s] = o0;
            out_off[b*3*SS + 1*SS + s] = o1;
            out_off[b*3*SS + 2*SS + s] = o2;
            float nxx = fx + o0, nyy = fy + o1, nzz = fz + o2;
            g_nodeloc[id*3+0] = nxx;
            g_nodeloc[id*3+1] = nyy;
            g_nodeloc[id*3+2] = nzz;
            snode[0] = nxx; snode[1] = nyy; snode[2] = nzz;
            snode[3] = __fmaf_rn(nzz, nzz, __fmaf_rn(nyy, nyy, __fmul_rn(nxx, nxx)));
        }
    }
    __syncthreads();
    float nx = snode[0], ny = snode[1], nz = snode[2], ns2 = snode[3];
    const float4* X4 = (const float4*)L;
    const float4* Y4 = (const float4*)(L + NN);
    const float4* Z4 = (const float4*)(L + 2*NN);
    // pass A: 12-bit histogram of keys, float4-vectorized (keys not stored)
    for (int g = tid; g < NN/4; g += 256) {
        float4 xv = X4[g], yv = Y4[g], zv = Z4[g];
        atomicAdd(&hist[key_xyz(xv.x, yv.x, zv.x, nx, ny, nz, ns2) >> 20], 1);
        atomicAdd(&hist[key_xyz(xv.y, yv.y, zv.y, nx, ny, nz, ns2) >> 20], 1);
        atomicAdd(&hist[key_xyz(xv.z, yv.z, zv.z, nx, ny, nz, ns2) >> 20], 1);
        atomicAdd(&hist[key_xyz(xv.w, yv.w, zv.w, nx, ny, nz, ns2) >> 20], 1);
    }
    __syncthreads();
    pick_bins(hist, 16, 64, tid, lane, wid, s_w8, &sbin, &skk);
    unsigned bin12 = sbin; int k2 = skk;
    // pass B: recompute keys (float4), warp-uniform early skip, compact
    for (int g = tid; g < NN/4; g += 256) {
        float4 xv = X4[g], yv = Y4[g], zv = Z4[g];
        unsigned kk[4];
        kk[0] = key_xyz(xv.x, yv.x, zv.x, nx, ny, nz, ns2);
        kk[1] = key_xyz(xv.y, yv.y, zv.y, nx, ny, nz, ns2);
        kk[2] = key_xyz(xv.z, yv.z, zv.z, nx, ny, nz, ns2);
        kk[3] = key_xyz(xv.w, yv.w, zv.w, nx, ny, nz, ns2);
        bool act = (kk[0] >> 20) <= bin12 || (kk[1] >> 20) <= bin12 ||
                   (kk[2] >> 20) <= bin12 || (kk[3] >> 20) <= bin12;
        if (!__ballot_sync(0xffffffffu, act)) continue;   // ~96% of warp-iters skip
#pragma unroll
        for (int i = 0; i < 4; ++i) {
            unsigned key = kk[i];
            int n = g*4 + i;
            unsigned hi = key >> 20;
            bool lt = (hi < bin12), eqp = (hi == bin12);
            unsigned mlt = __ballot_sync(0xffffffffu, lt);
            unsigned meq = __ballot_sync(0xffffffffu, eqp);
            if (!(mlt | meq)) continue;                   // warp-uniform
            int bl = 0, be = 0;
            if (lane == 0) {
                if (mlt) bl = atomicAdd(&scnt, __popc(mlt));
                if (meq) be = atomicAdd(&ccnt, __popc(meq));
            }
            bl = __shfl_sync(0xffffffffu, bl, 0);
            be = __shfl_sync(0xffffffffu, be, 0);
            if (lt)  { int p = bl + __popc(mlt & lml); if (p < 64) sel[p] = n; }
            if (eqp) { int p = be + __popc(meq & lml);
                       if (p < 1024) { cand[p] = n; candk[p] = key; } }
        }
    }
    __syncthreads();
    unsigned T;
    int nc = ccnt;
    if (nc <= 1024) {
        // refine on candidates: bits 19:10 then 9:0
        for (int i = tid; i < 1024; i += 256) hist[i] = 0;
        __syncthreads();
        for (int i = tid; i < nc; i += 256) atomicAdd(&hist[(candk[i] >> 10) & 0x3FFu], 1);
        __syncthreads();
        pick_bins(hist, 4, k2, tid, lane, wid, s_w8, &sbin, &skk);
        unsigned bin10a = sbin; int k3 = skk;
        for (int i = tid; i < 1024; i += 256) hist[i] = 0;
        __syncthreads();
        for (int i = tid; i < nc; i += 256) {
            unsigned key = candk[i];
            if (((key >> 10) & 0x3FFu) == bin10a) atomicAdd(&hist[key & 0x3FFu], 1);
        }
        __syncthreads();
        pick_bins(hist, 4, k3, tid, lane, wid, s_w8, &sbin, &skk);
        T = (bin12 << 20) | (bin10a << 10) | sbin;
        for (int i = tid; i < nc; i += 256) {
            unsigned key = candk[i];
            if (key < T)       { int p = atomicAdd(&scnt, 1); if (p < 64) sel[p] = cand[i]; }
            else if (key == T) { int p = atomicAdd(&eqcnt, 1); if (p < 128) eq[p] = cand[i]; }
        }
        __syncthreads();
        int need = 64 - scnt;
        if (eqcnt == need) {
            if (tid < need) sel[scnt + tid] = eq[tid];
        } else if (tid == 0) {
            int p = scnt, last = -1;
            for (int r = 0; r < need; ++r) {
                int best = 0x7fffffff;
                for (int i = 0; i < nc; ++i) {
                    int ix = cand[i];
                    if (candk[i] == T && ix > last && ix < best) best = ix;
                }
                sel[p++] = best; last = best;
            }
        }
        __syncthreads();
    } else {
        // rare fallback: full-scan refine of low 20 bits in 8/8/4 chunks
        int kf = k2;
        if (tid < 256) hist[tid] = 0;
        __syncthreads();
        for (int n = tid; n < NN; n += 256) {
            unsigned key = dist_key(L, n, nx, ny, nz, ns2);
            if ((key >> 20) == bin12) atomicAdd(&hist[(key >> 12) & 0xFFu], 1);
        }
        __syncthreads();
        pick_bins(hist, 1, kf, tid, lane, wid, s_w8, &sbin, &skk);
        unsigned pref1 = (bin12 << 8) | sbin; kf = skk;     // = key>>12
        if (tid < 256) hist[tid] = 0;
        __syncthreads();
        for (int n = tid; n < NN; n += 256) {
            unsigned key = dist_key(L, n, nx, ny, nz, ns2);
            if ((key >> 12) == pref1) atomicAdd(&hist[(key >> 4) & 0xFFu], 1);
        }
        __syncthreads();
        pick_bins(hist, 1, kf, tid, lane, wid, s_w8, &sbin, &skk);
        unsigned pref2 = (pref1 << 8) | sbin; kf = skk;     // = key>>4
        if (tid < 256) hist[tid] = 0;
        __syncthreads();
        for (int n = tid; n < NN; n += 256) {
            unsigned key = dist_key(L, n, nx, ny, nz, ns2);
            if ((key >> 4) == pref2) atomicAdd(&hist[key & 0xFu], 1);
        }
        __syncthreads();
        pick_bins(hist, 1, kf, tid, lane, wid, s_w8, &sbin, &skk);
        T = (pref2 << 4) | sbin;
        for (int n = tid; n < NN; n += 256) {
            unsigned key = dist_key(L, n, nx, ny, nz, ns2);
            if ((key >> 20) == bin12 && key < T) {
                int p = atomicAdd(&scnt, 1); if (p < 64) sel[p] = n;
            } else if (key == T) {
                int p = atomicAdd(&eqcnt, 1); if (p < 128) eq[p] = n;
            }
        }
        __syncthreads();
        int need = 64 - scnt;
        if (eqcnt == need) {
            if (tid < need) sel[scnt + tid] = eq[tid];
        } else if (tid == 0) {
            int p = scnt, last = -1;
            for (int r = 0; r < need; ++r) {
                int best = 0x7fffffff;
                for (int n = 0; n < NN; ++n)
                    if (dist_key(L, n, nx, ny, nz, ns2) == T && n > last && n < best) best = n;
                sel[p++] = best; last = best;
            }
        }
        __syncthreads();
    }

    // node_fea: per-channel max/min over selected 64, then BN affine + relu
    int ch = tid & 63, grp = tid >> 6;
    float mx = -CUDART_INF_F, mn = CUDART_INF_F;
    const float* YT = g_yT + (size_t)b*NN*CC;
    for (int k = grp; k < 64; k += 4) {
        float v = YT[(size_t)sel[k]*CC + ch];
        mx = fmaxf(mx, v); mn = fminf(mn, v);
    }
    smx[tid] = mx; smn[tid] = mn;
    __syncthreads();
    if (grp == 0) {
        mx = fmaxf(fmaxf(smx[ch], smx[ch+64]), fmaxf(smx[ch+128], smx[ch+192]));
        mn = fminf(fminf(smn[ch], smn[ch+64]), fminf(smn[ch+128], smn[ch+192]));
        float cnt  = (float)(BB*NN);
        float mean = g_sum[ch] / cnt;
        float var  = g_sq[ch] / cnt - mean*mean;
        float a    = gamma[ch] / sqrtf(var + 1e-5f);
        float c    = beta[ch] - mean * a;
        float m = (a >= 0.f) ? mx : mn;
        float val = fmaxf(fmaf(a, m, c), 0.f);
        out_nf[(size_t)b*CC*SS + ch*SS + s] = val;
    }
}

// ---------------- K4: 3-NN interpolation into output channels 64..127 -----
__global__ void __launch_bounds__(256) k_upsample(const float* __restrict__ loc,
                                                  const float* __restrict__ nf,
                                                  float* __restrict__ out) {
    __shared__ float snx[SS], sny[SS], snz[SS], sns[SS];
    __shared__ float snf[CC*SS];
    int b = blockIdx.y;
    int tid = threadIdx.x;
    int n = blockIdx.x * 256 + tid;
    if (tid < SS) {
        float x = g_nodeloc[(b*SS+tid)*3];
        float y = g_nodeloc[(b*SS+tid)*3+1];
        float z = g_nodeloc[(b*SS+tid)*3+2];
        snx[tid] = x; sny[tid] = y; snz[tid] = z;
        sns[tid] = __fmaf_rn(z, z, __fmaf_rn(y, y, __fmul_rn(x, x)));
    }
    for (int i = tid; i < CC*SS; i += 256) snf[i] = nf[(size_t)b*CC*SS + i];
    __syncthreads();
    const float* L = loc + (size_t)b*3*NN;
    float x = L[n], y = L[NN+n], z = L[2*NN+n];
    float ps2 = __fmaf_rn(z, z, __fmaf_rn(y, y, __fmul_rn(x, x)));
    float d0 = CUDART_INF_F, d1 = CUDART_INF_F, d2 = CUDART_INF_F;
    int i0 = 0, i1 = 0, i2 = 0;
#pragma unroll 4
    for (int sj = 0; sj < SS; ++sj) {
        float dot = __fmaf_rn(snz[sj], z, __fmaf_rn(sny[sj], y, __fmul_rn(snx[sj], x)));
        float d   = __fadd_rn(__fadd_rn(__fmul_rn(-2.f, dot), ps2), sns[sj]);
        if (d < d0)      { d2 = d1; i2 = i1; d1 = d0; i1 = i0; d0 = d; i0 = sj; }
        else if (d < d1) { d2 = d1; i2 = i1; d1 = d;  i1 = sj; }
        else if (d < d2) { d2 = d;  i2 = sj; }
    }
    d0 = fmaxf(d0, 1e-10f); d1 = fmaxf(d1, 1e-10f); d2 = fmaxf(d2, 1e-10f);
    float w0 = 1.f/d0, w1 = 1.f/d1, w2 = 1.f/d2;
    float ws = (w0 + w1) + w2;
    w0 /= ws; w1 /= ws; w2 /= ws;
    float* O = out + ((size_t)b*2*CC + CC)*NN + n;
    for (int c = 0; c < CC; ++c) {
        float v = fmaf(w2, snf[c*SS+i2], fmaf(w1, snf[c*SS+i1], w0*snf[c*SS+i0]));
        O[(size_t)c*NN] = v;
    }
}

extern "C" void kernel_launch(void* const* d_in, const int* in_sizes, int n_in,
                              void* d_out, int out_size) {
    const float* fea   = (const float*)d_in[0];
    const float* loc   = (const float*)d_in[1];
    const float* Woff  = (const float*)d_in[2];
    const float* Wres  = (const float*)d_in[3];
    const float* bres  = (const float*)d_in[4];
    const float* gamma = (const float*)d_in[5];
    const float* beta  = (const float*)d_in[6];
    float* out = (float*)d_out;
    float* out_nf  = out + (size_t)BB*2*CC*NN;
    float* out_off = out_nf + (size_t)BB*CC*SS;

    static cudaStream_t s_side = 0;
    static cudaEvent_t  e_fork = 0, e_join = 0;
    if (s_side == 0) {
        cudaStreamCreateWithFlags(&s_side, cudaStreamNonBlocking);
        cudaEventCreateWithFlags(&e_fork, cudaEventDisableTiming);
        cudaEventCreateWithFlags(&e_join, cudaEventDisableTiming);
        cudaFuncSetAttribute(k_fps, cudaFuncAttributeMaxDynamicSharedMemorySize, 3*NN*4);
    }

    k_zero<<<1, 64>>>();
    // fork: fps (low occupancy) runs concurrently with gemm (independent data)
    cudaEventRecord(e_fork, 0);
    cudaStreamWaitEvent(s_side, e_fork, 0);
    k_fps<<<BB, 1024, 3*NN*4, s_side>>>(loc);
    k_gemm<<<dim3(64, BB), 256>>>(fea, Wres, bres, Woff, out);
    // join: select needs both g_fidx (fps) and yT/proj/stats (gemm)
    cudaEventRecord(e_join, s_side);
    cudaStreamWaitEvent(0, e_join, 0);
    k_select<<<BB*SS, 256>>>(loc, gamma, beta, out_nf, out_off);
    k_upsample<<<dim3(NN/256, BB), 256>>>(loc, out_nf, out);
}

// round 17
// speedup vs baseline: 1.1573x; 1.1573x over previous
#include <cuda_runtime.h>
#include <math_constants.h>

#define BB 32
#define CC 64
#define NN 8192
#define SS 64

typedef unsigned long long ull;

// ---------------- device scratch ----------------
__device__ float g_yT[(size_t)BB*NN*CC];    // conv output transposed: [b][n][c]
__device__ float g_proj[(size_t)BB*3*NN];   // W_off @ fea: [b][3][n]
__device__ float g_nodeloc[BB*SS*3];
__device__ int   g_fidx[BB*SS];
__device__ float g_sum[CC];
__device__ float g_sq[CC];

__device__ __forceinline__ void cp_async16(void* smem_dst, const void* gmem_src) {
    unsigned sa = (unsigned)__cvta_generic_to_shared(smem_dst);
    asm volatile("cp.async.ca.shared.global [%0], [%1], 16;" :: "r"(sa), "l"(gmem_src));
}
__device__ __forceinline__ void cp_commit() { asm volatile("cp.async.commit_group;"); }
__device__ __forceinline__ void cp_wait0()  { asm volatile("cp.async.wait_group 0;"); }

// ---- f32x2 helpers (lanewise FFMA pair; bit-identical to 2x scalar fmaf) --
__device__ __forceinline__ ull bcast2(float f) {
    ull r; asm("mov.b64 %0,{%1,%1};" : "=l"(r) : "f"(f)); return r;
}
__device__ __forceinline__ void fma2(ull &acc, ull a, ull b) {
    asm("fma.rn.f32x2 %0,%1,%2,%0;" : "+l"(acc) : "l"(a), "l"(b));
}
__device__ __forceinline__ void unpack2(ull v, float &lo, float &hi) {
    asm("mov.b64 {%0,%1},%2;" : "=f"(lo), "=f"(hi) : "l"(v));
}

// ---------------- K0: zero BN accumulators ----------------
__global__ void k_zero() {
    int i = threadIdx.x;
    if (i < CC) { g_sum[i] = 0.f; g_sq[i] = 0.f; }
}

// ---------------- K1: farthest point sampling (loc staged in smem) --------
__device__ __forceinline__ void amax2(float &v, int &i, float v2, int i2) {
    if (v2 > v || (v2 == v && i2 < i)) { v = v2; i = i2; }
}

__global__ void k_fps(const float* __restrict__ loc) {
    extern __shared__ float sloc[];         // [3*NN] = 96KB
    int b = blockIdx.x;
    int t = threadIdx.x;
    const float* L = loc + (size_t)b*3*NN;
    for (int i = t; i < 3*NN; i += 1024) sloc[i] = L[i];
    __shared__ float swv[32];
    __shared__ int   swi[32];
    __shared__ int   s_far;
    if (t == 0) s_far = 0;
    __syncthreads();
    float px[8], py[8], pz[8], pd[8];
#pragma unroll
    for (int j = 0; j < 8; ++j) {
        int n = j*1024 + t;
        px[j] = sloc[n]; py[j] = sloc[NN+n]; pz[j] = sloc[2*NN+n];
        pd[j] = 1e10f;
    }
    int lane = t & 31, wid = t >> 5;
    for (int it = 0; it < SS; ++it) {
        int far = s_far;
        if (t == 0) g_fidx[b*SS + it] = far;
        float cx = sloc[far], cy = sloc[NN+far], cz = sloc[2*NN+far];
        float bv = -1.f; int bi = 0;
#pragma unroll
        for (int j = 0; j < 8; ++j) {
            float dx = px[j] - cx;
            float dy = py[j] - cy;
            float dz = pz[j] - cz;
            float d  = __fmaf_rn(dz, dz, __fmaf_rn(dy, dy, __fmul_rn(dx, dx)));
            float nd = fminf(pd[j], d);
            pd[j] = nd;
            if (nd > bv) { bv = nd; bi = j*1024 + t; }
        }
#pragma unroll
        for (int off = 16; off; off >>= 1) {
            float v2 = __shfl_down_sync(0xffffffffu, bv, off);
            int   i2 = __shfl_down_sync(0xffffffffu, bi, off);
            amax2(bv, bi, v2, i2);
        }
        if (lane == 0) { swv[wid] = bv; swi[wid] = bi; }
        __syncthreads();
        if (wid == 0) {
            bv = swv[lane]; bi = swi[lane];
#pragma unroll
            for (int off = 16; off; off >>= 1) {
                float v2 = __shfl_down_sync(0xffffffffu, bv, off);
                int   i2 = __shfl_down_sync(0xffffffffu, bi, off);
                amax2(bv, bi, v2, i2);
            }
            if (lane == 0) s_far = bi;
        }
        __syncthreads();
    }
}

// ---------------- K2: fused GEMM + proj + copy-out + BN stats -------------
// n_t=4: each thread computes 16 channels x 4 n-columns. Weight LDS traffic
// per MAC halved vs n_t=2 (L1 was 82% -> the measured bottleneck).
__global__ void __launch_bounds__(256, 2) k_gemm(const float* __restrict__ fea,
                                                 const float* __restrict__ Wres,
                                                 const float* __restrict__ bres,
                                                 const float* __restrict__ Woff,
                                                 float* __restrict__ out) {
    __shared__ float sWt[CC*CC];        // transposed: [c][o], 16KB
    __shared__ float sWo[3*CC];
    __shared__ float sF[2][8*256];      // 8KB per buffer
    __shared__ float sstat[2*CC];
    int b = blockIdx.y, base = blockIdx.x * 256, tid = threadIdx.x;
    for (int i = tid; i < CC*CC; i += 256) { int o = i >> 6, c = i & 63; sWt[c*CC + o] = Wres[i]; }
    for (int i = tid; i < 3*CC; i += 256) sWo[i] = Woff[i];
    if (tid < 2*CC) sstat[tid] = 0.f;
    int ogrp = tid >> 6, nl = tid & 63, o0 = ogrp * 16;
    int lane = tid & 31;
    const float* F = fea + (size_t)b*CC*NN + base;
    float* O0 = out + (size_t)b*2*CC*NN + base;
    int lc = tid >> 5;                  // channel row 0..7 within chunk
    int lcol = (tid & 31) * 4;          // first float4 col; second at +128
    ull acc[4][8];
#pragma unroll
    for (int j = 0; j < 4; ++j)
#pragma unroll
        for (int q = 0; q < 8; ++q) acc[j][q] = 0ull;
    float pj[3][4];
#pragma unroll
    for (int o = 0; o < 3; ++o)
#pragma unroll
        for (int j = 0; j < 4; ++j) pj[o][j] = 0.f;
    cp_async16(&sF[0][lc*256 + lcol], &F[(size_t)lc*NN + lcol]);
    cp_async16(&sF[0][lc*256 + 128 + lcol], &F[(size_t)lc*NN + 128 + lcol]);
    cp_commit();
    for (int ch = 0; ch < 8; ++ch) {
        int buf = ch & 1;
        cp_wait0();
        __syncthreads();
        if (ch < 7) {
            cp_async16(&sF[buf^1][lc*256 + lcol], &F[(size_t)((ch+1)*8 + lc)*NN + lcol]);
            cp_async16(&sF[buf^1][lc*256 + 128 + lcol], &F[(size_t)((ch+1)*8 + lc)*NN + 128 + lcol]);
            cp_commit();
        }
        // copy-out this chunk to output channels 0..63
        *(float4*)&O0[(size_t)(ch*8 + lc)*NN + lcol] = *(float4*)&sF[buf][lc*256 + lcol];
        *(float4*)&O0[(size_t)(ch*8 + lc)*NN + 128 + lcol] = *(float4*)&sF[buf][lc*256 + 128 + lcol];
#pragma unroll
        for (int cc = 0; cc < 8; ++cc) {
            int c = ch*8 + cc;
            float f0 = sF[buf][cc*256 + nl];
            float f1 = sF[buf][cc*256 + 64 + nl];
            float f2 = sF[buf][cc*256 + 128 + nl];
            float f3 = sF[buf][cc*256 + 192 + nl];
            const longlong2* W2 = (const longlong2*)&sWt[c*CC + o0];  // 16 floats = 8 ull
            longlong2 wa = W2[0], wb = W2[1], wc = W2[2], wd = W2[3];
            ull ff0 = bcast2(f0), ff1 = bcast2(f1), ff2 = bcast2(f2), ff3 = bcast2(f3);
            fma2(acc[0][0], (ull)wa.x, ff0); fma2(acc[1][0], (ull)wa.x, ff1);
            fma2(acc[2][0], (ull)wa.x, ff2); fma2(acc[3][0], (ull)wa.x, ff3);
            fma2(acc[0][1], (ull)wa.y, ff0); fma2(acc[1][1], (ull)wa.y, ff1);
            fma2(acc[2][1], (ull)wa.y, ff2); fma2(acc[3][1], (ull)wa.y, ff3);
            fma2(acc[0][2], (ull)wb.x, ff0); fma2(acc[1][2], (ull)wb.x, ff1);
            fma2(acc[2][2], (ull)wb.x, ff2); fma2(acc[3][2], (ull)wb.x, ff3);
            fma2(acc[0][3], (ull)wb.y, ff0); fma2(acc[1][3], (ull)wb.y, ff1);
            fma2(acc[2][3], (ull)wb.y, ff2); fma2(acc[3][3], (ull)wb.y, ff3);
            fma2(acc[0][4], (ull)wc.x, ff0); fma2(acc[1][4], (ull)wc.x, ff1);
            fma2(acc[2][4], (ull)wc.x, ff2); fma2(acc[3][4], (ull)wc.x, ff3);
            fma2(acc[0][5], (ull)wc.y, ff0); fma2(acc[1][5], (ull)wc.y, ff1);
            fma2(acc[2][5], (ull)wc.y, ff2); fma2(acc[3][5], (ull)wc.y, ff3);
            fma2(acc[0][6], (ull)wd.x, ff0); fma2(acc[1][6], (ull)wd.x, ff1);
            fma2(acc[2][6], (ull)wd.x, ff2); fma2(acc[3][6], (ull)wd.x, ff3);
            fma2(acc[0][7], (ull)wd.y, ff0); fma2(acc[1][7], (ull)wd.y, ff1);
            fma2(acc[2][7], (ull)wd.y, ff2); fma2(acc[3][7], (ull)wd.y, ff3);
            if (ogrp == 1) {
                float v0 = sWo[c], v1 = sWo[64+c], v2 = sWo[128+c];
                pj[0][0] = fmaf(v0, f0, pj[0][0]); pj[0][1] = fmaf(v0, f1, pj[0][1]);
                pj[0][2] = fmaf(v0, f2, pj[0][2]); pj[0][3] = fmaf(v0, f3, pj[0][3]);
                pj[1][0] = fmaf(v1, f0, pj[1][0]); pj[1][1] = fmaf(v1, f1, pj[1][1]);
                pj[1][2] = fmaf(v1, f2, pj[1][2]); pj[1][3] = fmaf(v1, f3, pj[1][3]);
                pj[2][0] = fmaf(v2, f0, pj[2][0]); pj[2][1] = fmaf(v2, f1, pj[2][1]);
                pj[2][2] = fmaf(v2, f2, pj[2][2]); pj[2][3] = fmaf(v2, f3, pj[2][3]);
            }
        }
    }
    if (ogrp == 1) {
        float* P = g_proj + (size_t)b*3*NN + base + nl;
#pragma unroll
        for (int j = 0; j < 4; ++j) {
            P[j*64]        = pj[0][j];
            P[NN + j*64]   = pj[1][j];
            P[2*NN + j*64] = pj[2][j];
        }
    }
    float bb[16];
#pragma unroll
    for (int q = 0; q < 16; ++q) bb[q] = bres[o0+q];
    float s1v[16], s2v[16];
#pragma unroll
    for (int q = 0; q < 16; ++q) { s1v[q] = 0.f; s2v[q] = 0.f; }
    float* YT = g_yT + (size_t)b*NN*CC;
#pragma unroll
    for (int j = 0; j < 4; ++j) {
        float v[16];
#pragma unroll
        for (int q = 0; q < 8; ++q) unpack2(acc[j][q], v[2*q], v[2*q+1]);
#pragma unroll
        for (int q = 0; q < 16; ++q) {
            v[q] = v[q] + bb[q];
            s1v[q] += v[q];
            s2v[q] = fmaf(v[q], v[q], s2v[q]);
        }
        float4* dst = (float4*)(YT + (size_t)(base + j*64 + nl)*CC + o0);
        dst[0] = make_float4(v[0],v[1],v[2],v[3]);
        dst[1] = make_float4(v[4],v[5],v[6],v[7]);
        dst[2] = make_float4(v[8],v[9],v[10],v[11]);
        dst[3] = make_float4(v[12],v[13],v[14],v[15]);
    }
#pragma unroll
    for (int off = 16; off; off >>= 1)
#pragma unroll
        for (int q = 0; q < 16; ++q) {
            s1v[q] += __shfl_xor_sync(0xffffffffu, s1v[q], off);
            s2v[q] += __shfl_xor_sync(0xffffffffu, s2v[q], off);
        }
    if (lane == 0) {
#pragma unroll
        for (int q = 0; q < 16; ++q) {
            atomicAdd(&sstat[o0+q], s1v[q]);
            atomicAdd(&sstat[64+o0+q], s2v[q]);
        }
    }
    __syncthreads();
    if (tid < 64)       atomicAdd(&g_sum[tid], sstat[tid]);
    else if (tid < 128) atomicAdd(&g_sq[tid-64], sstat[tid]);
}

// ---------------- bin picker: block-wide k-th bin over nbpt*256 bins ------
__device__ __forceinline__ void pick_bins(const int* h, int nbpt, int kwant,
                                          int tid, int lane, int wid,
                                          int* s_w8, unsigned* sbin, int* skk) {
    int base = tid * nbpt;
    int ssum = 0;
    for (int i = 0; i < nbpt; ++i) ssum += h[base+i];
    int inc = ssum;
#pragma unroll
    for (int off = 1; off < 32; off <<= 1) {
        int v = __shfl_up_sync(0xffffffffu, inc, off);
        if (lane >= off) inc += v;
    }
    if (lane == 31) s_w8[wid] = inc;
    __syncthreads();
    if (wid == 0 && lane < 8) {
        int y = s_w8[lane];
#pragma unroll
        for (int off = 1; off < 8; off <<= 1) {
            int v = __shfl_up_sync(0x000000ffu, y, off);
            if (lane >= off) y += v;
        }
        s_w8[lane] = y;
    }
    __syncthreads();
    int pre = inc - ssum + (wid ? s_w8[wid-1] : 0);
    if (pre < kwant && pre + ssum >= kwant) {
        int cum = pre;
        for (int i = 0; i < nbpt; ++i) {
            int hv = h[base+i];
            if (cum + hv >= kwant) { *sbin = (unsigned)(base+i); *skk = kwant - cum; break; }
            cum += hv;
        }
    }
    __syncthreads();
}

// order-preserving key from xyz; single definition -> bit-identical everywhere
__device__ __forceinline__ unsigned key_xyz(float x, float y, float z,
                                            float nx, float ny, float nz, float ns2) {
    float dot = __fmaf_rn(nz, z, __fmaf_rn(ny, y, __fmul_rn(nx, x)));
    float ps2 = __fmaf_rn(z, z, __fmaf_rn(y, y, __fmul_rn(x, x)));
    float d   = __fadd_rn(__fadd_rn(__fmul_rn(-2.f, dot), ns2), ps2);
    unsigned u = __float_as_uint(d);
    return (u & 0x80000000u) ? ~u : (u | 0x80000000u);
}
__device__ __forceinline__ unsigned dist_key(const float* __restrict__ L, int n,
                                             float nx, float ny, float nz, float ns2) {
    return key_xyz(L[n], L[NN+n], L[2*NN+n], nx, ny, nz, ns2);
}

// ------ K3: fused ball-query offset + 64-NN select + node_fea -------------
__global__ void __launch_bounds__(256) k_select(const float* __restrict__ loc,
                                                const float* __restrict__ gamma,
                                                const float* __restrict__ beta,
                                                float* __restrict__ out_nf,
                                                float* __restrict__ out_off) {
    __shared__ int hist[4096];             // 16KB (reused at 1024/256 granularity)
    __shared__ int cand[1024];
    __shared__ unsigned candk[1024];
    __shared__ int sel[64];
    __shared__ int eq[128];
    __shared__ int bsel[64];
    __shared__ float snode[4];
    __shared__ int s_w8[8];
    __shared__ unsigned sbin;
    __shared__ int skk;
    __shared__ int scnt, ccnt, eqcnt;
    __shared__ float smx[256], smn[256];
    int id = blockIdx.x;
    int b = id >> 6, s = id & 63;
    int tid = threadIdx.x;
    int lane = tid & 31, wid = tid >> 5;
    unsigned lml = (1u << lane) - 1u;
    const float* L = loc + (size_t)b*3*NN;

    // warps 1..7 zero hist + counters while warp 0 does ball query + offset
    if (wid > 0) {
        for (int i = tid - 32; i < 4096; i += 224) hist[i] = 0;
        if (tid == 32) { scnt = 0; ccnt = 0; eqcnt = 0; }
    } else {
        const float* P = g_proj + (size_t)b*3*NN;
        int nidx = g_fidx[id];
        float fx = L[nidx], fy = L[NN+nidx], fz = L[2*NN+nidx];
        float fs2 = __fmaf_rn(fz, fz, __fmaf_rn(fy, fy, __fmul_rn(fx, fx)));
        const float r2 = (float)(0.3*0.3);
        int cnt = 0;
        for (int basei = 0; basei < NN && cnt < 64; basei += 32) {
            int n = basei + lane;
            float x = L[n], y = L[NN+n], z = L[2*NN+n];
            float dot = __fmaf_rn(fz, z, __fmaf_rn(fy, y, __fmul_rn(fx, x)));
            float ps2 = __fmaf_rn(z, z, __fmaf_rn(y, y, __fmul_rn(x, x)));
            float d   = __fadd_rn(__fadd_rn(__fmul_rn(-2.f, dot), fs2), ps2);
            bool ok = !(d > r2);
            unsigned m = __ballot_sync(0xffffffffu, ok);
            int pos = cnt + __popc(m & lml);
            if (ok && pos < 64) bsel[pos] = n;
            cnt += __popc(m);
        }
        if (cnt > 64) cnt = 64;
        __syncwarp();
        for (int k = cnt + lane; k < 64; k += 32) bsel[k] = bsel[0];
        __syncwarp();
        float p0n = P[nidx], p1n = P[NN+nidx], p2n = P[2*NN+nidx];
        float a0 = 0.f, a1 = 0.f, a2 = 0.f;
#pragma unroll
        for (int k = lane; k < 64; k += 32) {
            int idx = bsel[k];
            float t0 = tanhf(P[idx]      - p0n);
            float t1 = tanhf(P[NN+idx]   - p1n);
            float t2 = tanhf(P[2*NN+idx] - p2n);
            a0 = fmaf(t0, L[idx] - fx, a0);
            a1 = fmaf(t1, L[NN+idx] - fy, a1);
            a2 = fmaf(t2, L[2*NN+idx] - fz, a2);
        }
#pragma unroll
        for (int off = 16; off; off >>= 1) {
            a0 += __shfl_xor_sync(0xffffffffu, a0, off);
            a1 += __shfl_xor_sync(0xffffffffu, a1, off);
            a2 += __shfl_xor_sync(0xffffffffu, a2, off);
        }
        if (lane == 0) {
            float o0 = a0 * (1.f/64.f), o1 = a1 * (1.f/64.f), o2 = a2 * (1.f/64.f);
            out_off[b*3*SS + 0*SS + s] = o0;
            out_off[b*3*SS + 1*SS + s] = o1;
            out_off[b*3*SS + 2*SS + s] = o2;
            float nxx = fx + o0, nyy = fy + o1, nzz = fz + o2;
            g_nodeloc[id*3+0] = nxx;
            g_nodeloc[id*3+1] = nyy;
            g_nodeloc[id*3+2] = nzz;
            snode[0] = nxx; snode[1] = nyy; snode[2] = nzz;
            snode[3] = __fmaf_rn(nzz, nzz, __fmaf_rn(nyy, nyy, __fmul_rn(nxx, nxx)));
        }
    }
    __syncthreads();
    float nx = snode[0], ny = snode[1], nz = snode[2], ns2 = snode[3];
    const float4* X4 = (const float4*)L;
    const float4* Y4 = (const float4*)(L + NN);
    const float4* Z4 = (const float4*)(L + 2*NN);
    // pass A: 12-bit histogram of keys, float4-vectorized (keys not stored)
    for (int g = tid; g < NN/4; g += 256) {
        float4 xv = X4[g], yv = Y4[g], zv = Z4[g];
        atomicAdd(&hist[key_xyz(xv.x, yv.x, zv.x, nx, ny, nz, ns2) >> 20], 1);
        atomicAdd(&hist[key_xyz(xv.y, yv.y, zv.y, nx, ny, nz, ns2) >> 20], 1);
        atomicAdd(&hist[key_xyz(xv.z, yv.z, zv.z, nx, ny, nz, ns2) >> 20], 1);
        atomicAdd(&hist[key_xyz(xv.w, yv.w, zv.w, nx, ny, nz, ns2) >> 20], 1);
    }
    __syncthreads();
    pick_bins(hist, 16, 64, tid, lane, wid, s_w8, &sbin, &skk);
    unsigned bin12 = sbin; int k2 = skk;
    // pass B: recompute keys (float4), compact via warp-aggregated atomics
    for (int g = tid; g < NN/4; g += 256) {
        float4 xv = X4[g], yv = Y4[g], zv = Z4[g];
        unsigned kk[4];
        kk[0] = key_xyz(xv.x, yv.x, zv.x, nx, ny, nz, ns2);
        kk[1] = key_xyz(xv.y, yv.y, zv.y, nx, ny, nz, ns2);
        kk[2] = key_xyz(xv.z, yv.z, zv.z, nx, ny, nz, ns2);
        kk[3] = key_xyz(xv.w, yv.w, zv.w, nx, ny, nz, ns2);
#pragma unroll
        for (int i = 0; i < 4; ++i) {
            unsigned key = kk[i];
            int n = g*4 + i;
            unsigned hi = key >> 20;
            bool lt = (hi < bin12), eqp = (hi == bin12);
            unsigned mlt = __ballot_sync(0xffffffffu, lt);
            unsigned meq = __ballot_sync(0xffffffffu, eqp);
            int bl = 0, be = 0;
            if (lane == 0) {
                if (mlt) bl = atomicAdd(&scnt, __popc(mlt));
                if (meq) be = atomicAdd(&ccnt, __popc(meq));
            }
            bl = __shfl_sync(0xffffffffu, bl, 0);
            be = __shfl_sync(0xffffffffu, be, 0);
            if (lt)  { int p = bl + __popc(mlt & lml); if (p < 64) sel[p] = n; }
            if (eqp) { int p = be + __popc(meq & lml);
                       if (p < 1024) { cand[p] = n; candk[p] = key; } }
        }
    }
    __syncthreads();
    unsigned T;
    int nc = ccnt;
    if (nc <= 1024) {
        // refine on candidates: bits 19:10 then 9:0
        for (int i = tid; i < 1024; i += 256) hist[i] = 0;
        __syncthreads();
        for (int i = tid; i < nc; i += 256) atomicAdd(&hist[(candk[i] >> 10) & 0x3FFu], 1);
        __syncthreads();
        pick_bins(hist, 4, k2, tid, lane, wid, s_w8, &sbin, &skk);
        unsigned bin10a = sbin; int k3 = skk;
        for (int i = tid; i < 1024; i += 256) hist[i] = 0;
        __syncthreads();
        for (int i = tid; i < nc; i += 256) {
            unsigned key = candk[i];
            if (((key >> 10) & 0x3FFu) == bin10a) atomicAdd(&hist[key & 0x3FFu], 1);
        }
        __syncthreads();
        pick_bins(hist, 4, k3, tid, lane, wid, s_w8, &sbin, &skk);
        T = (bin12 << 20) | (bin10a << 10) | sbin;
        for (int i = tid; i < nc; i += 256) {
            unsigned key = candk[i];
            if (key < T)       { int p = atomicAdd(&scnt, 1); if (p < 64) sel[p] = cand[i]; }
            else if (key == T) { int p = atomicAdd(&eqcnt, 1); if (p < 128) eq[p] = cand[i]; }
        }
        __syncthreads();
        int need = 64 - scnt;
        if (eqcnt == need) {
            if (tid < need) sel[scnt + tid] = eq[tid];
        } else if (tid == 0) {
            int p = scnt, last = -1;
            for (int r = 0; r < need; ++r) {
                int best = 0x7fffffff;
                for (int i = 0; i < nc; ++i) {
                    int ix = cand[i];
                    if (candk[i] == T && ix > last && ix < best) best = ix;
                }
                sel[p++] = best; last = best;
            }
        }
        __syncthreads();
    } else {
        // rare fallback: full-scan refine of low 20 bits in 8/8/4 chunks
        int kf = k2;
        if (tid < 256) hist[tid] = 0;
        __syncthreads();
        for (int n = tid; n < NN; n += 256) {
            unsigned key = dist_key(L, n, nx, ny, nz, ns2);
            if ((key >> 20) == bin12) atomicAdd(&hist[(key >> 12) & 0xFFu], 1);
        }
        __syncthreads();
        pick_bins(hist, 1, kf, tid, lane, wid, s_w8, &sbin, &skk);
        unsigned pref1 = (bin12 << 8) | sbin; kf = skk;     // = key>>12
        if (tid < 256) hist[tid] = 0;
        __syncthreads();
        for (int n = tid; n < NN; n += 256) {
            unsigned key = dist_key(L, n, nx, ny, nz, ns2);
            if ((key >> 12) == pref1) atomicAdd(&hist[(key >> 4) & 0xFFu], 1);
        }
        __syncthreads();
        pick_bins(hist, 1, kf, tid, lane, wid, s_w8, &sbin, &skk);
        unsigned pref2 = (pref1 << 8) | sbin; kf = skk;     // = key>>4
        if (tid < 256) hist[tid] = 0;
        __syncthreads();
        for (int n = tid; n < NN; n += 256) {
            unsigned key = dist_key(L, n, nx, ny, nz, ns2);
            if ((key >> 4) == pref2) atomicAdd(&hist[key & 0xFu], 1);
        }
        __syncthreads();
        pick_bins(hist, 1, kf, tid, lane, wid, s_w8, &sbin, &skk);
        T = (pref2 << 4) | sbin;
        for (int n = tid; n < NN; n += 256) {
            unsigned key = dist_key(L, n, nx, ny, nz, ns2);
            if ((key >> 20) == bin12 && key < T) {
                int p = atomicAdd(&scnt, 1); if (p < 64) sel[p] = n;
            } else if (key == T) {
                int p = atomicAdd(&eqcnt, 1); if (p < 128) eq[p] = n;
            }
        }
        __syncthreads();
        int need = 64 - scnt;
        if (eqcnt == need) {
            if (tid < need) sel[scnt + tid] = eq[tid];
        } else if (tid == 0) {
            int p = scnt, last = -1;
            for (int r = 0; r < need; ++r) {
                int best = 0x7fffffff;
                for (int n = 0; n < NN; ++n)
                    if (dist_key(L, n, nx, ny, nz, ns2) == T && n > last && n < best) best = n;
                sel[p++] = best; last = best;
            }
        }
        __syncthreads();
    }

    // node_fea: per-channel max/min over selected 64, then BN affine + relu
    int ch = tid & 63, grp = tid >> 6;
    float mx = -CUDART_INF_F, mn = CUDART_INF_F;
    const float* YT = g_yT + (size_t)b*NN*CC;
    for (int k = grp; k < 64; k += 4) {
        float v = YT[(size_t)sel[k]*CC + ch];
        mx = fmaxf(mx, v); mn = fminf(mn, v);
    }
    smx[tid] = mx; smn[tid] = mn;
    __syncthreads();
    if (grp == 0) {
        mx = fmaxf(fmaxf(smx[ch], smx[ch+64]), fmaxf(smx[ch+128], smx[ch+192]));
        mn = fminf(fminf(smn[ch], smn[ch+64]), fminf(smn[ch+128], smn[ch+192]));
        float cnt  = (float)(BB*NN);
        float mean = g_sum[ch] / cnt;
        float var  = g_sq[ch] / cnt - mean*mean;
        float a    = gamma[ch] / sqrtf(var + 1e-5f);
        float c    = beta[ch] - mean * a;
        float m = (a >= 0.f) ? mx : mn;
        float val = fmaxf(fmaf(a, m, c), 0.f);
        out_nf[(size_t)b*CC*SS + ch*SS + s] = val;
    }
}

// ---------------- K4: 3-NN interpolation into output channels 64..127 -----
__global__ void __launch_bounds__(256) k_upsample(const float* __restrict__ loc,
                                                  const float* __restrict__ nf,
                                                  float* __restrict__ out) {
    __shared__ float snx[SS], sny[SS], snz[SS], sns[SS];
    __shared__ float snf[CC*SS];
    int b = blockIdx.y;
    int tid = threadIdx.x;
    int n = blockIdx.x * 256 + tid;
    if (tid < SS) {
        float x = g_nodeloc[(b*SS+tid)*3];
        float y = g_nodeloc[(b*SS+tid)*3+1];
        float z = g_nodeloc[(b*SS+tid)*3+2];
        snx[tid] = x; sny[tid] = y; snz[tid] = z;
        sns[tid] = __fmaf_rn(z, z, __fmaf_rn(y, y, __fmul_rn(x, x)));
    }
    for (int i = tid; i < CC*SS; i += 256) snf[i] = nf[(size_t)b*CC*SS + i];
    __syncthreads();
    const float* L = loc + (size_t)b*3*NN;
    float x = L[n], y = L[NN+n], z = L[2*NN+n];
    float ps2 = __fmaf_rn(z, z, __fmaf_rn(y, y, __fmul_rn(x, x)));
    float d0 = CUDART_INF_F, d1 = CUDART_INF_F, d2 = CUDART_INF_F;
    int i0 = 0, i1 = 0, i2 = 0;
#pragma unroll 4
    for (int sj = 0; sj < SS; ++sj) {
        float dot = __fmaf_rn(snz[sj], z, __fmaf_rn(sny[sj], y, __fmul_rn(snx[sj], x)));
        float d   = __fadd_rn(__fadd_rn(__fmul_rn(-2.f, dot), ps2), sns[sj]);
        if (d < d0)      { d2 = d1; i2 = i1; d1 = d0; i1 = i0; d0 = d; i0 = sj; }
        else if (d < d1) { d2 = d1; i2 = i1; d1 = d;  i1 = sj; }
        else if (d < d2) { d2 = d;  i2 = sj; }
    }
    d0 = fmaxf(d0, 1e-10f); d1 = fmaxf(d1, 1e-10f); d2 = fmaxf(d2, 1e-10f);
    float w0 = 1.f/d0, w1 = 1.f/d1, w2 = 1.f/d2;
    float ws = (w0 + w1) + w2;
    w0 /= ws; w1 /= ws; w2 /= ws;
    float* O = out + ((size_t)b*2*CC + CC)*NN + n;
    for (int c = 0; c < CC; ++c) {
        float v = fmaf(w2, snf[c*SS+i2], fmaf(w1, snf[c*SS+i1], w0*snf[c*SS+i0]));
        O[(size_t)c*NN] = v;
    }
}

extern "C" void kernel_launch(void* const* d_in, const int* in_sizes, int n_in,
                              void* d_out, int out_size) {
    const float* fea   = (const float*)d_in[0];
    const float* loc   = (const float*)d_in[1];
    const float* Woff  = (const float*)d_in[2];
    const float* Wres  = (const float*)d_in[3];
    const float* bres  = (const float*)d_in[4];
    const float* gamma = (const float*)d_in[5];
    const float* beta  = (const float*)d_in[6];
    float* out = (float*)d_out;
    float* out_nf  = out + (size_t)BB*2*CC*NN;
    float* out_off = out_nf + (size_t)BB*CC*SS;

    static cudaStream_t s_side = 0;
    static cudaEvent_t  e_fork = 0, e_join = 0;
    if (s_side == 0) {
        cudaStreamCreateWithFlags(&s_side, cudaStreamNonBlocking);
        cudaEventCreateWithFlags(&e_fork, cudaEventDisableTiming);
        cudaEventCreateWithFlags(&e_join, cudaEventDisableTiming);
        cudaFuncSetAttribute(k_fps, cudaFuncAttributeMaxDynamicSharedMemorySize, 3*NN*4);
    }

    k_zero<<<1, 64>>>();                                  // 1
    k_zero<<<1, 64>>>();                                  // 2 (filler: gemm -> slot 4)
    // fork: fps (low occupancy) runs concurrently with gemm (independent data)
    cudaEventRecord(e_fork, 0);
    cudaStreamWaitEvent(s_side, e_fork, 0);
    k_fps<<<BB, 1024, 3*NN*4, s_side>>>(loc);             // 3 side
    k_gemm<<<dim3(32, BB), 256>>>(fea, Wres, bres, Woff, out);  // 4 <- profiled
    // join: select needs both g_fidx (fps) and yT/proj/stats (gemm)
    cudaEventRecord(e_join, s_side);
    cudaStreamWaitEvent(0, e_join, 0);
    k_select<<<BB*SS, 256>>>(loc, gamma, beta, out_nf, out_off);
    k_upsample<<<dim3(NN/256, BB), 256>>>(loc, out_nf, out);
}